// round 1
// baseline (speedup 1.0000x reference)
#include <cuda_runtime.h>

#define N_NODES 32768
#define N_EDGES 524288
#define DIM     256
#define DBIG    1024
#define BATCH_B 128
#define NODES_PER 256

// ---------------- scratch (static device allocations are allowed) -----------
__device__ int   g_odeg[N_NODES];
__device__ int   g_ideg[N_NODES];
__device__ int   g_rowptr[N_NODES + 1];
__device__ int   g_cursor[N_NODES];
__device__ int   g_colidx[N_EDGES];
__device__ float g_ns[N_NODES];
__device__ float g_nd[N_NODES];
__device__ float g_hs  [N_NODES * DIM];    // ns-scaled features (input to aggregation)
__device__ float g_agg [N_NODES * DIM];    // aggregated * nd (input to GEMM)
__device__ float g_hbig[N_NODES * DBIG];   // layer-4 output
__device__ float g_pool[BATCH_B * DBIG];   // pooled + LN

// ---------------- graph setup ----------------------------------------------
__global__ void k_zero() {
    int i = blockIdx.x * blockDim.x + threadIdx.x;
    if (i < N_NODES) { g_odeg[i] = 0; g_ideg[i] = 0; }
}

__global__ void k_count(const int* __restrict__ src, const int* __restrict__ dst) {
    int e = blockIdx.x * blockDim.x + threadIdx.x;
    if (e < N_EDGES) {
        atomicAdd(&g_odeg[src[e]], 1);
        atomicAdd(&g_ideg[dst[e]], 1);
    }
}

// exclusive scan of g_ideg -> g_rowptr / g_cursor.  1 block of 1024 threads.
__global__ void k_scan() {
    __shared__ int part[1024];
    int tid = threadIdx.x;
    int loc[32];
    int s = 0;
#pragma unroll
    for (int i = 0; i < 32; ++i) { loc[i] = g_ideg[tid * 32 + i]; s += loc[i]; }
    part[tid] = s;
    __syncthreads();
    for (int off = 1; off < 1024; off <<= 1) {
        int v = (tid >= off) ? part[tid - off] : 0;
        __syncthreads();
        part[tid] += v;
        __syncthreads();
    }
    int excl = part[tid] - s;
#pragma unroll
    for (int i = 0; i < 32; ++i) {
        g_rowptr[tid * 32 + i] = excl;
        g_cursor[tid * 32 + i] = excl;
        excl += loc[i];
    }
    if (tid == 1023) g_rowptr[N_NODES] = part[1023];
}

__global__ void k_scatter(const int* __restrict__ src, const int* __restrict__ dst) {
    int e = blockIdx.x * blockDim.x + threadIdx.x;
    if (e < N_EDGES) {
        int p = atomicAdd(&g_cursor[dst[e]], 1);
        g_colidx[p] = src[e];
    }
}

__global__ void k_norms() {
    int i = blockIdx.x * blockDim.x + threadIdx.x;
    if (i < N_NODES) {
        int od = g_odeg[i], id = g_ideg[i];
        g_ns[i] = (od > 0) ? rsqrtf((float)od) : 1.0f;
        g_nd[i] = (id > 0) ? rsqrtf((float)id) : 1.0f;
    }
}

// hs = x * ns   (float4 granularity; 32768*64 float4s)
__global__ void k_scale_x(const float* __restrict__ x, float* __restrict__ hs) {
    int i = blockIdx.x * blockDim.x + threadIdx.x;   // float4 index
    if (i < N_NODES * (DIM / 4)) {
        int row = i >> 6;
        float s = g_ns[row];
        float4 v = *(const float4*)&x[i * 4];
        v.x *= s; v.y *= s; v.z *= s; v.w *= s;
        *(float4*)&hs[i * 4] = v;
    }
}

// ---------------- aggregation: agg[dst] = nd[dst] * sum hs[src] -------------
// 4 nodes per 256-thread block; 64 threads (float4 lanes) per node.
__global__ void __launch_bounds__(256) k_aggregate(const float* __restrict__ hs,
                                                   float* __restrict__ agg) {
    int node = blockIdx.x * 4 + (threadIdx.x >> 6);
    int c = (threadIdx.x & 63) * 4;
    int beg = g_rowptr[node], end = g_rowptr[node + 1];
    float4 acc = make_float4(0.f, 0.f, 0.f, 0.f);
    int e = beg;
    for (; e + 4 <= end; e += 4) {
        int s0 = g_colidx[e + 0], s1 = g_colidx[e + 1];
        int s2 = g_colidx[e + 2], s3 = g_colidx[e + 3];
        float4 v0 = *(const float4*)&hs[s0 * DIM + c];
        float4 v1 = *(const float4*)&hs[s1 * DIM + c];
        float4 v2 = *(const float4*)&hs[s2 * DIM + c];
        float4 v3 = *(const float4*)&hs[s3 * DIM + c];
        acc.x += (v0.x + v1.x) + (v2.x + v3.x);
        acc.y += (v0.y + v1.y) + (v2.y + v3.y);
        acc.z += (v0.z + v1.z) + (v2.z + v3.z);
        acc.w += (v0.w + v1.w) + (v2.w + v3.w);
    }
    for (; e < end; ++e) {
        int s0 = g_colidx[e];
        float4 v0 = *(const float4*)&hs[s0 * DIM + c];
        acc.x += v0.x; acc.y += v0.y; acc.z += v0.z; acc.w += v0.w;
    }
    float nd = g_nd[node];
    acc.x *= nd; acc.y *= nd; acc.z *= nd; acc.w *= nd;
    *(float4*)&agg[node * DIM + c] = acc;
}

// ---------------- GEMM (f32x2 packed FMA) + fused leaky/LN/ns epilogue ------
// Block: 256 threads = 16(tx) x 16(ty).  Tile: M=64, N=256, KC=32.
// Thread owns rows ty*4+i (i<4), cols c*64 + tx*4 + j (c<4, j<4).
#define KC 32
#define AS_STR 72   // padded k-major A tile stride (floats); 288B = 16B-aligned rows

template <bool FUSE_LN>
__global__ void __launch_bounds__(256, 2) k_gemm(
    const float* __restrict__ A, const float* __restrict__ W,
    const float* __restrict__ bias, float* __restrict__ out, int N, int K)
{
    __shared__ float As[KC * AS_STR];
    __shared__ float Bs[KC * 256];
    int tid = threadIdx.x;
    int tx = tid & 15, ty = tid >> 4;
    int m0 = blockIdx.y * 64;
    int n0 = blockIdx.x * 256;

    unsigned long long acc2[4][4][2];
#pragma unroll
    for (int i = 0; i < 4; ++i)
#pragma unroll
        for (int c = 0; c < 4; ++c) { acc2[i][c][0] = 0ULL; acc2[i][c][1] = 0ULL; }

    for (int k0 = 0; k0 < K; k0 += KC) {
        // A tile: 64 rows x 32 k, stored transposed As[k][m]
#pragma unroll
        for (int t = 0; t < 2; ++t) {
            int s = tid + t * 256;          // 0..511
            int row = s >> 3;               // 0..63
            int kq = s & 7;                 // 0..7
            float4 v = *(const float4*)&A[(m0 + row) * K + k0 + kq * 4];
            As[(kq * 4 + 0) * AS_STR + row] = v.x;
            As[(kq * 4 + 1) * AS_STR + row] = v.y;
            As[(kq * 4 + 2) * AS_STR + row] = v.z;
            As[(kq * 4 + 3) * AS_STR + row] = v.w;
        }
        // B tile: 32 k x 256 n
#pragma unroll
        for (int t = 0; t < 8; ++t) {
            int s = tid + t * 256;          // float4 slots 0..2047
            int kr = s >> 6;                // 0..31
            int c4 = s & 63;                // 0..63
            *(float4*)&Bs[kr * 256 + c4 * 4] =
                *(const float4*)&W[(k0 + kr) * N + n0 + c4 * 4];
        }
        __syncthreads();
#pragma unroll
        for (int k = 0; k < KC; ++k) {
            float4 a4 = *(const float4*)&As[k * AS_STR + ty * 4];
            unsigned long long a2[4];
            unsigned int au0 = __float_as_uint(a4.x), au1 = __float_as_uint(a4.y);
            unsigned int au2 = __float_as_uint(a4.z), au3 = __float_as_uint(a4.w);
            asm("mov.b64 %0, {%1,%1};" : "=l"(a2[0]) : "r"(au0));
            asm("mov.b64 %0, {%1,%1};" : "=l"(a2[1]) : "r"(au1));
            asm("mov.b64 %0, {%1,%1};" : "=l"(a2[2]) : "r"(au2));
            asm("mov.b64 %0, {%1,%1};" : "=l"(a2[3]) : "r"(au3));
#pragma unroll
            for (int c = 0; c < 4; ++c) {
                ulonglong2 bb = *(const ulonglong2*)&Bs[k * 256 + c * 64 + tx * 4];
#pragma unroll
                for (int i = 0; i < 4; ++i) {
                    asm("fma.rn.f32x2 %0, %1, %2, %0;"
                        : "+l"(acc2[i][c][0]) : "l"(a2[i]), "l"(bb.x));
                    asm("fma.rn.f32x2 %0, %1, %2, %0;"
                        : "+l"(acc2[i][c][1]) : "l"(a2[i]), "l"(bb.y));
                }
            }
        }
        __syncthreads();
    }

    // unpack + bias
    float accf[4][16];
#pragma unroll
    for (int i = 0; i < 4; ++i)
#pragma unroll
        for (int c = 0; c < 4; ++c)
#pragma unroll
            for (int h = 0; h < 2; ++h) {
                float lo, hi;
                asm("mov.b64 {%0,%1}, %2;" : "=f"(lo), "=f"(hi) : "l"(acc2[i][c][h]));
                accf[i][c * 4 + h * 2 + 0] = lo;
                accf[i][c * 4 + h * 2 + 1] = hi;
            }
    float bv[16];
#pragma unroll
    for (int c = 0; c < 4; ++c) {
        float4 b4 = *(const float4*)&bias[n0 + c * 64 + tx * 4];
        bv[c * 4 + 0] = b4.x; bv[c * 4 + 1] = b4.y;
        bv[c * 4 + 2] = b4.z; bv[c * 4 + 3] = b4.w;
    }

    if (FUSE_LN) {
        // N == 256, gridDim.x == 1: each row lives in one half-warp (16 lanes)
#pragma unroll
        for (int i = 0; i < 4; ++i) {
            float v[16];
            float s = 0.f, q = 0.f;
#pragma unroll
            for (int j = 0; j < 16; ++j) {
                float t = accf[i][j] + bv[j];
                t = (t >= 0.f) ? t : 0.01f * t;          // leaky relu
                v[j] = t; s += t; q += t * t;
            }
#pragma unroll
            for (int off = 1; off < 16; off <<= 1) {
                s += __shfl_xor_sync(0xffffffffu, s, off);
                q += __shfl_xor_sync(0xffffffffu, q, off);
            }
            float mean = s * (1.0f / 256.0f);
            float var = q * (1.0f / 256.0f) - mean * mean;
            float rstd = rsqrtf(var + 1e-5f);
            int row = m0 + ty * 4 + i;
            float sc = g_ns[row] * rstd;                 // fold next-layer ns scaling
#pragma unroll
            for (int c = 0; c < 4; ++c) {
                float4 o;
                o.x = (v[c * 4 + 0] - mean) * sc;
                o.y = (v[c * 4 + 1] - mean) * sc;
                o.z = (v[c * 4 + 2] - mean) * sc;
                o.w = (v[c * 4 + 3] - mean) * sc;
                *(float4*)&out[row * N + c * 64 + tx * 4] = o;
            }
        }
    } else {
#pragma unroll
        for (int i = 0; i < 4; ++i) {
            int row = m0 + ty * 4 + i;
#pragma unroll
            for (int c = 0; c < 4; ++c) {
                float4 o;
                o.x = accf[i][c * 4 + 0] + bv[c * 4 + 0];
                o.y = accf[i][c * 4 + 1] + bv[c * 4 + 1];
                o.z = accf[i][c * 4 + 2] + bv[c * 4 + 2];
                o.w = accf[i][c * 4 + 3] + bv[c * 4 + 3];
                *(float4*)&out[row * N + n0 + c * 64 + tx * 4] = o;
            }
        }
    }
}

// ---------------- leaky + LN over 1024-wide rows (in place), warp per row ---
__global__ void __launch_bounds__(256) k_ln_big(float* __restrict__ h) {
    int row = blockIdx.x * 8 + (threadIdx.x >> 5);
    int lane = threadIdx.x & 31;
    float* r = h + row * DBIG;
    float4 v[8];
    float s = 0.f, q = 0.f;
#pragma unroll
    for (int t = 0; t < 8; ++t) {
        float4 x4 = *(const float4*)&r[lane * 4 + t * 128];
        x4.x = (x4.x >= 0.f) ? x4.x : 0.01f * x4.x;
        x4.y = (x4.y >= 0.f) ? x4.y : 0.01f * x4.y;
        x4.z = (x4.z >= 0.f) ? x4.z : 0.01f * x4.z;
        x4.w = (x4.w >= 0.f) ? x4.w : 0.01f * x4.w;
        v[t] = x4;
        s += (x4.x + x4.y) + (x4.z + x4.w);
        q += (x4.x * x4.x + x4.y * x4.y) + (x4.z * x4.z + x4.w * x4.w);
    }
#pragma unroll
    for (int off = 1; off < 32; off <<= 1) {
        s += __shfl_xor_sync(0xffffffffu, s, off);
        q += __shfl_xor_sync(0xffffffffu, q, off);
    }
    float mean = s * (1.0f / 1024.0f);
    float var = q * (1.0f / 1024.0f) - mean * mean;
    float rstd = rsqrtf(var + 1e-5f);
#pragma unroll
    for (int t = 0; t < 8; ++t) {
        float4 o;
        o.x = (v[t].x - mean) * rstd; o.y = (v[t].y - mean) * rstd;
        o.z = (v[t].z - mean) * rstd; o.w = (v[t].w - mean) * rstd;
        *(float4*)&r[lane * 4 + t * 128] = o;
    }
}

// ---------------- mean-pool over 256 nodes + LN, one block per batch row ----
__global__ void __launch_bounds__(256) k_pool(const float* __restrict__ h,
                                              float* __restrict__ pool) {
    int b = blockIdx.x;
    int tid = threadIdx.x;
    const float* base = h + b * NODES_PER * DBIG;
    float4 acc = make_float4(0.f, 0.f, 0.f, 0.f);
#pragma unroll 4
    for (int j = 0; j < NODES_PER; ++j) {
        float4 x4 = *(const float4*)&base[j * DBIG + tid * 4];
        acc.x += x4.x; acc.y += x4.y; acc.z += x4.z; acc.w += x4.w;
    }
    const float inv = 1.0f / (float)NODES_PER;
    float v0 = acc.x * inv, v1 = acc.y * inv, v2 = acc.z * inv, v3 = acc.w * inv;
    float s = (v0 + v1) + (v2 + v3);
    float q = (v0 * v0 + v1 * v1) + (v2 * v2 + v3 * v3);
#pragma unroll
    for (int off = 1; off < 32; off <<= 1) {
        s += __shfl_xor_sync(0xffffffffu, s, off);
        q += __shfl_xor_sync(0xffffffffu, q, off);
    }
    __shared__ float ss[8], qq[8];
    __shared__ float s_mean, s_rstd;
    int wid = tid >> 5, lane = tid & 31;
    if (lane == 0) { ss[wid] = s; qq[wid] = q; }
    __syncthreads();
    if (tid == 0) {
        float S = 0.f, Q = 0.f;
#pragma unroll
        for (int w = 0; w < 8; ++w) { S += ss[w]; Q += qq[w]; }
        float mean = S * (1.0f / 1024.0f);
        float var = Q * (1.0f / 1024.0f) - mean * mean;
        s_mean = mean;
        s_rstd = rsqrtf(var + 1e-5f);
    }
    __syncthreads();
    float mean = s_mean, rstd = s_rstd;
    float4 o;
    o.x = (v0 - mean) * rstd; o.y = (v1 - mean) * rstd;
    o.z = (v2 - mean) * rstd; o.w = (v3 - mean) * rstd;
    *(float4*)&pool[b * DBIG + tid * 4] = o;
}

// ---------------- heads: init output with bias, then split-K GEMM ----------
__global__ void k_out_init(const float* __restrict__ bm, const float* __restrict__ bs,
                           float* __restrict__ out) {
    int i = blockIdx.x * blockDim.x + threadIdx.x;   // 0..262143
    if (i < 2 * BATCH_B * DBIG) {
        int n = i & (DBIG - 1);
        out[i] = (i < BATCH_B * DBIG) ? bm[n] : bs[n];
    }
}

// grid (16 ntiles, 8 kchunks, 2 heads); block 256.  Tile: 128 rows x 64 cols.
__global__ void __launch_bounds__(256) k_head(const float* __restrict__ pool,
                                              const float* __restrict__ Wm,
                                              const float* __restrict__ Ws,
                                              float* __restrict__ out) {
    const float* W = blockIdx.z ? Ws : Wm;
    float* o = out + blockIdx.z * (BATCH_B * DBIG);
    int n0 = blockIdx.x * 64;
    int kc0 = blockIdx.y * 128;
    int tid = threadIdx.x;
    int col = tid & 63;
    int ty = tid >> 6;                      // 0..3 -> rows ty*32..+32
    __shared__ float Ap[32 * 136];
    __shared__ float Wsm[32 * 64];
    float acc[32];
#pragma unroll
    for (int r = 0; r < 32; ++r) acc[r] = 0.f;

    for (int kk = 0; kk < 128; kk += 32) {
#pragma unroll
        for (int t = 0; t < 4; ++t) {
            int s = tid + t * 256;          // 0..1023 float4 slots
            int row = s >> 3, kq = s & 7;
            float4 v = *(const float4*)&pool[row * DBIG + kc0 + kk + kq * 4];
            Ap[(kq * 4 + 0) * 136 + row] = v.x;
            Ap[(kq * 4 + 1) * 136 + row] = v.y;
            Ap[(kq * 4 + 2) * 136 + row] = v.z;
            Ap[(kq * 4 + 3) * 136 + row] = v.w;
        }
#pragma unroll
        for (int t = 0; t < 2; ++t) {
            int s = tid + t * 256;          // 0..511 float4 slots
            int kr = s >> 4, c4 = s & 15;
            *(float4*)&Wsm[kr * 64 + c4 * 4] =
                *(const float4*)&W[(kc0 + kk + kr) * DBIG + n0 + c4 * 4];
        }
        __syncthreads();
#pragma unroll
        for (int k = 0; k < 32; ++k) {
            float b = Wsm[k * 64 + col];
#pragma unroll
            for (int r4 = 0; r4 < 8; ++r4) {
                float4 a = *(const float4*)&Ap[k * 136 + ty * 32 + r4 * 4];
                acc[r4 * 4 + 0] += a.x * b;
                acc[r4 * 4 + 1] += a.y * b;
                acc[r4 * 4 + 2] += a.z * b;
                acc[r4 * 4 + 3] += a.w * b;
            }
        }
        __syncthreads();
    }
#pragma unroll
    for (int r = 0; r < 32; ++r)
        atomicAdd(&o[(ty * 32 + r) * DBIG + n0 + col], acc[r]);
}

// ---------------- driver ----------------------------------------------------
extern "C" void kernel_launch(void* const* d_in, const int* in_sizes, int n_in,
                              void* d_out, int out_size) {
    const float* x   = (const float*)d_in[0];
    const int*   src = (const int*)d_in[1];
    const int*   dst = (const int*)d_in[2];
    const float* Wl[4] = { (const float*)d_in[3], (const float*)d_in[5],
                           (const float*)d_in[7], (const float*)d_in[9] };
    const float* bl[4] = { (const float*)d_in[4], (const float*)d_in[6],
                           (const float*)d_in[8], (const float*)d_in[10] };
    const float* Wm = (const float*)d_in[11];
    const float* bm = (const float*)d_in[12];
    const float* Ws = (const float*)d_in[13];
    const float* bs = (const float*)d_in[14];
    float* out = (float*)d_out;

    void *p_hs, *p_agg, *p_hbig, *p_pool;
    cudaGetSymbolAddress(&p_hs,   g_hs);
    cudaGetSymbolAddress(&p_agg,  g_agg);
    cudaGetSymbolAddress(&p_hbig, g_hbig);
    cudaGetSymbolAddress(&p_pool, g_pool);
    float* hs   = (float*)p_hs;
    float* agg  = (float*)p_agg;
    float* hbig = (float*)p_hbig;
    float* pool = (float*)p_pool;

    // graph preprocessing (rebuilt every call; captured in the graph)
    k_zero   <<<128, 256>>>();
    k_count  <<<2048, 256>>>(src, dst);
    k_scan   <<<1, 1024>>>();
    k_scatter<<<2048, 256>>>(src, dst);
    k_norms  <<<128, 256>>>();
    k_scale_x<<<8192, 256>>>(x, hs);

    // layers 1-3: aggregate -> GEMM(256x256) with fused leaky+LN+ns
    for (int l = 0; l < 3; ++l) {
        k_aggregate<<<N_NODES / 4, 256>>>(hs, agg);
        k_gemm<true><<<dim3(1, N_NODES / 64), 256>>>(agg, Wl[l], bl[l], hs, 256, 256);
    }
    // layer 4: aggregate -> GEMM(256x1024) -> leaky+LN (in place)
    k_aggregate<<<N_NODES / 4, 256>>>(hs, agg);
    k_gemm<false><<<dim3(4, N_NODES / 64), 256>>>(agg, Wl[3], bl[3], hbig, 1024, 256);
    k_ln_big<<<N_NODES / 8, 256>>>(hbig);

    // pool + LN, then heads
    k_pool<<<BATCH_B, 256>>>(hbig, pool);
    k_out_init<<<512, 512>>>(bm, bs, out);
    k_head<<<dim3(16, 8, 2), 256>>>(pool, Wm, Ws, out);
}

// round 3
// speedup vs baseline: 1.4771x; 1.4771x over previous
#include <cuda_runtime.h>
#include <cuda_bf16.h>
#include <cstdint>

#define N_NODES 32768
#define N_EDGES 524288
#define DIM     256
#define DBIG    1024
#define BATCH_B 128
#define NODES_PER 256

// ---------------- scratch ---------------------------------------------------
__device__ int   g_odeg[N_NODES];
__device__ int   g_ideg[N_NODES];
__device__ int   g_rowptr[N_NODES + 1];
__device__ int   g_cursor[N_NODES];
__device__ int   g_colidx[N_EDGES];
__device__ float g_ns[N_NODES];
__device__ float g_nd[N_NODES];
__device__ float g_hs  [N_NODES * DIM];     // LN'd + ns-scaled features (agg input)
__device__ float g_tmp [N_NODES * DIM];     // raw gemm output (bias only)
__device__ float g_hbig[N_NODES * DBIG];
__device__ float g_pool[BATCH_B * DBIG];
__device__ __nv_bfloat16 g_aggh[N_NODES * DIM];   // aggregated, bf16 hi
__device__ __nv_bfloat16 g_aggl[N_NODES * DIM];   // aggregated, bf16 lo
// transposed + split weights: B[n][k] = W[k][n], bf16 hi/lo, K-major (K=256)
#define WT_L4_OFF 196608
__device__ __nv_bfloat16 g_whT[196608 + 262144];
__device__ __nv_bfloat16 g_wlT[196608 + 262144];

// ---------------- helpers ---------------------------------------------------
__device__ __forceinline__ uint32_t smem_u32(const void* p) {
    uint32_t a;
    asm("{ .reg .u64 t; cvta.to.shared.u64 t, %1; cvt.u32.u64 %0, t; }" : "=r"(a) : "l"(p));
    return a;
}
#define LDSM4(r, addr)                                                          \
    asm volatile("ldmatrix.sync.aligned.m8n8.x4.shared.b16 {%0,%1,%2,%3}, [%4];"\
        : "=r"((r)[0]), "=r"((r)[1]), "=r"((r)[2]), "=r"((r)[3]) : "r"(addr))
#define MMA16816(d, a, b)                                                       \
    asm volatile("mma.sync.aligned.m16n8k16.row.col.f32.bf16.bf16.f32 "         \
        "{%0,%1,%2,%3},{%4,%5,%6,%7},{%8,%9},{%0,%1,%2,%3};"                    \
        : "+f"((d)[0]), "+f"((d)[1]), "+f"((d)[2]), "+f"((d)[3])                \
        : "r"((a)[0]), "r"((a)[1]), "r"((a)[2]), "r"((a)[3]),                   \
          "r"((b)[0]), "r"((b)[1]))

// ---------------- graph setup ------------------------------------------------
__global__ void k_zero() {
    int i = blockIdx.x * blockDim.x + threadIdx.x;
    if (i < N_NODES) { g_odeg[i] = 0; g_ideg[i] = 0; }
}
__global__ void k_count(const int* __restrict__ src, const int* __restrict__ dst) {
    int e = blockIdx.x * blockDim.x + threadIdx.x;
    if (e < N_EDGES) { atomicAdd(&g_odeg[src[e]], 1); atomicAdd(&g_ideg[dst[e]], 1); }
}
__global__ void k_scan() {
    __shared__ int part[1024];
    int tid = threadIdx.x;
    int loc[32];
    int s = 0;
#pragma unroll
    for (int i = 0; i < 32; ++i) { loc[i] = g_ideg[tid * 32 + i]; s += loc[i]; }
    part[tid] = s;
    __syncthreads();
    for (int off = 1; off < 1024; off <<= 1) {
        int v = (tid >= off) ? part[tid - off] : 0;
        __syncthreads();
        part[tid] += v;
        __syncthreads();
    }
    int excl = part[tid] - s;
#pragma unroll
    for (int i = 0; i < 32; ++i) {
        g_rowptr[tid * 32 + i] = excl;
        g_cursor[tid * 32 + i] = excl;
        excl += loc[i];
    }
    if (tid == 1023) g_rowptr[N_NODES] = part[1023];
}
__global__ void k_scatter(const int* __restrict__ src, const int* __restrict__ dst) {
    int e = blockIdx.x * blockDim.x + threadIdx.x;
    if (e < N_EDGES) { int p = atomicAdd(&g_cursor[dst[e]], 1); g_colidx[p] = src[e]; }
}
__global__ void k_norms() {
    int i = blockIdx.x * blockDim.x + threadIdx.x;
    if (i < N_NODES) {
        int od = g_odeg[i], id = g_ideg[i];
        g_ns[i] = (od > 0) ? rsqrtf((float)od) : 1.0f;
        g_nd[i] = (id > 0) ? rsqrtf((float)id) : 1.0f;
    }
}
__global__ void k_scale_x(const float* __restrict__ x, float* __restrict__ hs) {
    int i = blockIdx.x * blockDim.x + threadIdx.x;
    if (i < N_NODES * (DIM / 4)) {
        int row = i >> 6;
        float s = g_ns[row];
        float4 v = *(const float4*)&x[i * 4];
        v.x *= s; v.y *= s; v.z *= s; v.w *= s;
        *(float4*)&hs[i * 4] = v;
    }
}

// ---------------- weight transpose + bf16 split ------------------------------
__global__ void k_prep_w(const float* __restrict__ W, int N,
                         __nv_bfloat16* __restrict__ oh, __nv_bfloat16* __restrict__ ol) {
    __shared__ float t[32][33];
    int n = blockIdx.x * 32 + threadIdx.x;
    int kb = blockIdx.y * 32;
#pragma unroll
    for (int i = 0; i < 4; ++i) {
        int k = kb + threadIdx.y + i * 8;
        t[threadIdx.y + i * 8][threadIdx.x] = W[k * N + n];
    }
    __syncthreads();
    int k2 = kb + threadIdx.x;
#pragma unroll
    for (int i = 0; i < 4; ++i) {
        int n2 = blockIdx.x * 32 + threadIdx.y + i * 8;
        float v = t[threadIdx.x][threadIdx.y + i * 8];
        __nv_bfloat16 h = __float2bfloat16(v);
        oh[n2 * 256 + k2] = h;
        ol[n2 * 256 + k2] = __float2bfloat16(v - __bfloat162float(h));
    }
}

// ---------------- aggregation -> bf16 hi/lo split ----------------------------
__global__ void __launch_bounds__(256) k_aggregate(const float* __restrict__ hs,
                                                   __nv_bfloat16* __restrict__ aggh,
                                                   __nv_bfloat16* __restrict__ aggl) {
    int node = blockIdx.x * 4 + (threadIdx.x >> 6);
    int c = (threadIdx.x & 63) * 4;
    int beg = g_rowptr[node], end = g_rowptr[node + 1];
    float4 acc = make_float4(0.f, 0.f, 0.f, 0.f);
    int e = beg;
    for (; e + 4 <= end; e += 4) {
        int s0 = g_colidx[e + 0], s1 = g_colidx[e + 1];
        int s2 = g_colidx[e + 2], s3 = g_colidx[e + 3];
        float4 v0 = *(const float4*)&hs[s0 * DIM + c];
        float4 v1 = *(const float4*)&hs[s1 * DIM + c];
        float4 v2 = *(const float4*)&hs[s2 * DIM + c];
        float4 v3 = *(const float4*)&hs[s3 * DIM + c];
        acc.x += (v0.x + v1.x) + (v2.x + v3.x);
        acc.y += (v0.y + v1.y) + (v2.y + v3.y);
        acc.z += (v0.z + v1.z) + (v2.z + v3.z);
        acc.w += (v0.w + v1.w) + (v2.w + v3.w);
    }
    for (; e < end; ++e) {
        int s0 = g_colidx[e];
        float4 v0 = *(const float4*)&hs[s0 * DIM + c];
        acc.x += v0.x; acc.y += v0.y; acc.z += v0.z; acc.w += v0.w;
    }
    float nd = g_nd[node];
    acc.x *= nd; acc.y *= nd; acc.z *= nd; acc.w *= nd;
    __nv_bfloat162 h01 = __floats2bfloat162_rn(acc.x, acc.y);
    __nv_bfloat162 h23 = __floats2bfloat162_rn(acc.z, acc.w);
    __nv_bfloat162 l01 = __floats2bfloat162_rn(acc.x - __low2float(h01), acc.y - __high2float(h01));
    __nv_bfloat162 l23 = __floats2bfloat162_rn(acc.z - __low2float(h23), acc.w - __high2float(h23));
    uint2 hp = make_uint2(*(uint32_t*)&h01, *(uint32_t*)&h23);
    uint2 lp = make_uint2(*(uint32_t*)&l01, *(uint32_t*)&l23);
    *(uint2*)&aggh[node * DIM + c] = hp;
    *(uint2*)&aggl[node * DIM + c] = lp;
}

// ---------------- bf16 3-term mma.sync GEMM ----------------------------------
// CTA tile 128x128, 8 warps in 2(m) x 4(n), warp tile 64x32.  K in chunks of 32.
// A: [M][256] bf16 hi/lo (row-major).  B: [N][256] bf16 hi/lo (n-major, k contig).
#define APAD 40   // smem row stride (bf16) — 80B: conflict-free for ldmatrix

__global__ void __launch_bounds__(256, 2) k_gemm_mma(
    const __nv_bfloat16* __restrict__ Ah, const __nv_bfloat16* __restrict__ Al,
    const __nv_bfloat16* __restrict__ Bh, const __nv_bfloat16* __restrict__ Bl,
    const float* __restrict__ bias, float* __restrict__ out, int ldout)
{
    __shared__ __align__(16) __nv_bfloat16 sAh[128 * APAD];
    __shared__ __align__(16) __nv_bfloat16 sAl[128 * APAD];
    __shared__ __align__(16) __nv_bfloat16 sBh[128 * APAD];
    __shared__ __align__(16) __nv_bfloat16 sBl[128 * APAD];
    __shared__ float sBias[128];

    int tid = threadIdx.x;
    int wid = tid >> 5, lane = tid & 31;
    int m0 = blockIdx.y * 128, n0 = blockIdx.x * 128;
    int wm = (wid & 1) * 64, wn = (wid >> 1) * 32;

    if (tid < 128) sBias[tid] = bias[n0 + tid];

    float c[4][4][4];
#pragma unroll
    for (int i = 0; i < 4; ++i)
#pragma unroll
        for (int j = 0; j < 4; ++j) {
            c[i][j][0] = 0.f; c[i][j][1] = 0.f; c[i][j][2] = 0.f; c[i][j][3] = 0.f;
        }

    uint32_t uAh = smem_u32(sAh), uAl = smem_u32(sAl);
    uint32_t uBh = smem_u32(sBh), uBl = smem_u32(sBl);
    // per-lane ldmatrix address components (element units)
    int aRow = (wm + (lane & 15)) * APAD + (lane >> 4) * 8;
    int bRow = (wn + ((lane >> 4) & 1) * 8 + (lane & 7)) * APAD + ((lane >> 3) & 1) * 8;

    for (int k0 = 0; k0 < 256; k0 += 32) {
        // global -> smem: 128 rows x 32 k, uint4 = 8 bf16
#pragma unroll
        for (int it = 0; it < 2; ++it) {
            int s = tid + it * 256;
            int row = s >> 2, seg = s & 3;
            long gA = (long)(m0 + row) * 256 + k0 + seg * 8;
            long gB = (long)(n0 + row) * 256 + k0 + seg * 8;
            int so = row * APAD + seg * 8;
            *(uint4*)&sAh[so] = *(const uint4*)&Ah[gA];
            *(uint4*)&sAl[so] = *(const uint4*)&Al[gA];
            *(uint4*)&sBh[so] = *(const uint4*)&Bh[gB];
            *(uint4*)&sBl[so] = *(const uint4*)&Bl[gB];
        }
        __syncthreads();
#pragma unroll
        for (int kk = 0; kk < 2; ++kk) {
            int kb = kk * 16;
            // B frags for the warp's 32 columns (4 n8 groups), hi and lo
            uint32_t bh[4][2], bl[4][2];
#pragma unroll
            for (int nj2 = 0; nj2 < 2; ++nj2) {
                uint32_t off = (uint32_t)(bRow + nj2 * 16 * APAD + kb) * 2;
                uint32_t r[4];
                LDSM4(r, uBh + off);
                bh[nj2 * 2 + 0][0] = r[0]; bh[nj2 * 2 + 0][1] = r[1];
                bh[nj2 * 2 + 1][0] = r[2]; bh[nj2 * 2 + 1][1] = r[3];
                LDSM4(r, uBl + off);
                bl[nj2 * 2 + 0][0] = r[0]; bl[nj2 * 2 + 0][1] = r[1];
                bl[nj2 * 2 + 1][0] = r[2]; bl[nj2 * 2 + 1][1] = r[3];
            }
#pragma unroll
            for (int mi = 0; mi < 4; ++mi) {
                uint32_t off = (uint32_t)(aRow + mi * 16 * APAD + kb) * 2;
                uint32_t ah[4], al[4];
                LDSM4(ah, uAh + off);
                LDSM4(al, uAl + off);
#pragma unroll
                for (int n8 = 0; n8 < 4; ++n8) {
                    MMA16816(c[mi][n8], ah, bh[n8]);
                    MMA16816(c[mi][n8], ah, bl[n8]);
                    MMA16816(c[mi][n8], al, bh[n8]);
                }
            }
        }
        __syncthreads();
    }

    // epilogue: + bias, write fp32
    int lr = lane >> 2, lc = (lane & 3) * 2;
#pragma unroll
    for (int mi = 0; mi < 4; ++mi) {
#pragma unroll
        for (int n8 = 0; n8 < 4; ++n8) {
            int col = wn + n8 * 8 + lc;
            int row = m0 + wm + mi * 16 + lr;
            float b0 = sBias[col], b1 = sBias[col + 1];
            float2 v0 = make_float2(c[mi][n8][0] + b0, c[mi][n8][1] + b1);
            float2 v1 = make_float2(c[mi][n8][2] + b0, c[mi][n8][3] + b1);
            *(float2*)&out[(long)row * ldout + n0 + col] = v0;
            *(float2*)&out[(long)(row + 8) * ldout + n0 + col] = v1;
        }
    }
}

// ---------------- leaky + LN + ns over 256-wide rows -> hs -------------------
__global__ void __launch_bounds__(256) k_ln256(const float* __restrict__ in,
                                               float* __restrict__ hs) {
    int row = blockIdx.x * 8 + (threadIdx.x >> 5);
    int lane = threadIdx.x & 31;
    const float* r = in + (long)row * DIM;
    float4 v[2];
    float s = 0.f, q = 0.f;
#pragma unroll
    for (int t = 0; t < 2; ++t) {
        float4 x4 = *(const float4*)&r[lane * 4 + t * 128];
        x4.x = (x4.x >= 0.f) ? x4.x : 0.01f * x4.x;
        x4.y = (x4.y >= 0.f) ? x4.y : 0.01f * x4.y;
        x4.z = (x4.z >= 0.f) ? x4.z : 0.01f * x4.z;
        x4.w = (x4.w >= 0.f) ? x4.w : 0.01f * x4.w;
        v[t] = x4;
        s += (x4.x + x4.y) + (x4.z + x4.w);
        q += (x4.x * x4.x + x4.y * x4.y) + (x4.z * x4.z + x4.w * x4.w);
    }
#pragma unroll
    for (int off = 1; off < 32; off <<= 1) {
        s += __shfl_xor_sync(0xffffffffu, s, off);
        q += __shfl_xor_sync(0xffffffffu, q, off);
    }
    float mean = s * (1.0f / 256.0f);
    float var = q * (1.0f / 256.0f) - mean * mean;
    float sc = g_ns[row] * rsqrtf(var + 1e-5f);
    float* o = hs + (long)row * DIM;
#pragma unroll
    for (int t = 0; t < 2; ++t) {
        float4 w;
        w.x = (v[t].x - mean) * sc; w.y = (v[t].y - mean) * sc;
        w.z = (v[t].z - mean) * sc; w.w = (v[t].w - mean) * sc;
        *(float4*)&o[lane * 4 + t * 128] = w;
    }
}

// ---------------- leaky + LN over 1024-wide rows (in place) ------------------
__global__ void __launch_bounds__(256) k_ln_big(float* __restrict__ h) {
    int row = blockIdx.x * 8 + (threadIdx.x >> 5);
    int lane = threadIdx.x & 31;
    float* r = h + (long)row * DBIG;
    float4 v[8];
    float s = 0.f, q = 0.f;
#pragma unroll
    for (int t = 0; t < 8; ++t) {
        float4 x4 = *(const float4*)&r[lane * 4 + t * 128];
        x4.x = (x4.x >= 0.f) ? x4.x : 0.01f * x4.x;
        x4.y = (x4.y >= 0.f) ? x4.y : 0.01f * x4.y;
        x4.z = (x4.z >= 0.f) ? x4.z : 0.01f * x4.z;
        x4.w = (x4.w >= 0.f) ? x4.w : 0.01f * x4.w;
        v[t] = x4;
        s += (x4.x + x4.y) + (x4.z + x4.w);
        q += (x4.x * x4.x + x4.y * x4.y) + (x4.z * x4.z + x4.w * x4.w);
    }
#pragma unroll
    for (int off = 1; off < 32; off <<= 1) {
        s += __shfl_xor_sync(0xffffffffu, s, off);
        q += __shfl_xor_sync(0xffffffffu, q, off);
    }
    float mean = s * (1.0f / 1024.0f);
    float var = q * (1.0f / 1024.0f) - mean * mean;
    float rstd = rsqrtf(var + 1e-5f);
#pragma unroll
    for (int t = 0; t < 8; ++t) {
        float4 o;
        o.x = (v[t].x - mean) * rstd; o.y = (v[t].y - mean) * rstd;
        o.z = (v[t].z - mean) * rstd; o.w = (v[t].w - mean) * rstd;
        *(float4*)&r[lane * 4 + t * 128] = o;
    }
}

// ---------------- pool + LN --------------------------------------------------
__global__ void __launch_bounds__(256) k_pool(const float* __restrict__ h,
                                              float* __restrict__ pool) {
    int b = blockIdx.x;
    int tid = threadIdx.x;
    const float* base = h + (long)b * NODES_PER * DBIG;
    float4 acc = make_float4(0.f, 0.f, 0.f, 0.f);
#pragma unroll 4
    for (int j = 0; j < NODES_PER; ++j) {
        float4 x4 = *(const float4*)&base[(long)j * DBIG + tid * 4];
        acc.x += x4.x; acc.y += x4.y; acc.z += x4.z; acc.w += x4.w;
    }
    const float inv = 1.0f / (float)NODES_PER;
    float v0 = acc.x * inv, v1 = acc.y * inv, v2 = acc.z * inv, v3 = acc.w * inv;
    float s = (v0 + v1) + (v2 + v3);
    float q = (v0 * v0 + v1 * v1) + (v2 * v2 + v3 * v3);
#pragma unroll
    for (int off = 1; off < 32; off <<= 1) {
        s += __shfl_xor_sync(0xffffffffu, s, off);
        q += __shfl_xor_sync(0xffffffffu, q, off);
    }
    __shared__ float ss[8], qq[8];
    __shared__ float s_mean, s_rstd;
    int wid = tid >> 5, lane = tid & 31;
    if (lane == 0) { ss[wid] = s; qq[wid] = q; }
    __syncthreads();
    if (tid == 0) {
        float S = 0.f, Q = 0.f;
#pragma unroll
        for (int w = 0; w < 8; ++w) { S += ss[w]; Q += qq[w]; }
        float mean = S * (1.0f / 1024.0f);
        float var = Q * (1.0f / 1024.0f) - mean * mean;
        s_mean = mean;
        s_rstd = rsqrtf(var + 1e-5f);
    }
    __syncthreads();
    float mean = s_mean, rstd = s_rstd;
    float4 o;
    o.x = (v0 - mean) * rstd; o.y = (v1 - mean) * rstd;
    o.z = (v2 - mean) * rstd; o.w = (v3 - mean) * rstd;
    *(float4*)&pool[b * DBIG + tid * 4] = o;
}

// ---------------- heads ------------------------------------------------------
__global__ void k_out_init(const float* __restrict__ bm, const float* __restrict__ bs,
                           float* __restrict__ out) {
    int i = blockIdx.x * blockDim.x + threadIdx.x;
    if (i < 2 * BATCH_B * DBIG) {
        int n = i & (DBIG - 1);
        out[i] = (i < BATCH_B * DBIG) ? bm[n] : bs[n];
    }
}
__global__ void __launch_bounds__(256) k_head(const float* __restrict__ pool,
                                              const float* __restrict__ Wm,
                                              const float* __restrict__ Ws,
                                              float* __restrict__ out) {
    const float* W = blockIdx.z ? Ws : Wm;
    float* o = out + blockIdx.z * (BATCH_B * DBIG);
    int n0 = blockIdx.x * 64;
    int kc0 = blockIdx.y * 128;
    int tid = threadIdx.x;
    int col = tid & 63;
    int ty = tid >> 6;
    __shared__ float Ap[32 * 136];
    __shared__ float Wsm[32 * 64];
    float acc[32];
#pragma unroll
    for (int r = 0; r < 32; ++r) acc[r] = 0.f;

    for (int kk = 0; kk < 128; kk += 32) {
#pragma unroll
        for (int t = 0; t < 4; ++t) {
            int s = tid + t * 256;
            int row = s >> 3, kq = s & 7;
            float4 v = *(const float4*)&pool[row * DBIG + kc0 + kk + kq * 4];
            Ap[(kq * 4 + 0) * 136 + row] = v.x;
            Ap[(kq * 4 + 1) * 136 + row] = v.y;
            Ap[(kq * 4 + 2) * 136 + row] = v.z;
            Ap[(kq * 4 + 3) * 136 + row] = v.w;
        }
#pragma unroll
        for (int t = 0; t < 2; ++t) {
            int s = tid + t * 256;
            int kr = s >> 4, c4 = s & 15;
            *(float4*)&Wsm[kr * 64 + c4 * 4] =
                *(const float4*)&W[(kc0 + kk + kr) * DBIG + n0 + c4 * 4];
        }
        __syncthreads();
#pragma unroll
        for (int k = 0; k < 32; ++k) {
            float b = Wsm[k * 64 + col];
#pragma unroll
            for (int r4 = 0; r4 < 8; ++r4) {
                float4 a = *(const float4*)&Ap[k * 136 + ty * 32 + r4 * 4];
                acc[r4 * 4 + 0] += a.x * b;
                acc[r4 * 4 + 1] += a.y * b;
                acc[r4 * 4 + 2] += a.z * b;
                acc[r4 * 4 + 3] += a.w * b;
            }
        }
        __syncthreads();
    }
#pragma unroll
    for (int r = 0; r < 32; ++r)
        atomicAdd(&o[(ty * 32 + r) * DBIG + n0 + col], acc[r]);
}

// ---------------- driver ----------------------------------------------------
extern "C" void kernel_launch(void* const* d_in, const int* in_sizes, int n_in,
                              void* d_out, int out_size) {
    const float* x   = (const float*)d_in[0];
    const int*   src = (const int*)d_in[1];
    const int*   dst = (const int*)d_in[2];
    const float* Wl[4] = { (const float*)d_in[3], (const float*)d_in[5],
                           (const float*)d_in[7], (const float*)d_in[9] };
    const float* bl[4] = { (const float*)d_in[4], (const float*)d_in[6],
                           (const float*)d_in[8], (const float*)d_in[10] };
    const float* Wm = (const float*)d_in[11];
    const float* bm = (const float*)d_in[12];
    const float* Ws = (const float*)d_in[13];
    const float* bs = (const float*)d_in[14];
    float* out = (float*)d_out;

    void *p_hs, *p_tmp, *p_hbig, *p_pool, *p_wh, *p_wl, *p_ah, *p_al;
    cudaGetSymbolAddress(&p_hs,   g_hs);
    cudaGetSymbolAddress(&p_tmp,  g_tmp);
    cudaGetSymbolAddress(&p_hbig, g_hbig);
    cudaGetSymbolAddress(&p_pool, g_pool);
    cudaGetSymbolAddress(&p_wh,   g_whT);
    cudaGetSymbolAddress(&p_wl,   g_wlT);
    cudaGetSymbolAddress(&p_ah,   g_aggh);
    cudaGetSymbolAddress(&p_al,   g_aggl);
    float* hs   = (float*)p_hs;
    float* tmp  = (float*)p_tmp;
    float* hbig = (float*)p_hbig;
    float* pool = (float*)p_pool;
    __nv_bfloat16* whT = (__nv_bfloat16*)p_wh;
    __nv_bfloat16* wlT = (__nv_bfloat16*)p_wl;
    __nv_bfloat16* aggh = (__nv_bfloat16*)p_ah;
    __nv_bfloat16* aggl = (__nv_bfloat16*)p_al;

    // graph preprocessing
    k_zero   <<<128, 256>>>();
    k_count  <<<2048, 256>>>(src, dst);
    k_scan   <<<1, 1024>>>();
    k_scatter<<<2048, 256>>>(src, dst);
    k_norms  <<<128, 256>>>();
    k_scale_x<<<8192, 256>>>(x, hs);

    // weight transpose + split (bf16 hi/lo, [n][k])
    dim3 tb(32, 8);
    k_prep_w<<<dim3(8,  8), tb>>>(Wl[0], 256,  whT,            wlT);
    k_prep_w<<<dim3(8,  8), tb>>>(Wl[1], 256,  whT + 65536,    wlT + 65536);
    k_prep_w<<<dim3(8,  8), tb>>>(Wl[2], 256,  whT + 131072,   wlT + 131072);
    k_prep_w<<<dim3(32, 8), tb>>>(Wl[3], 1024, whT + WT_L4_OFF, wlT + WT_L4_OFF);

    // layers 1-3
    for (int l = 0; l < 3; ++l) {
        k_aggregate<<<N_NODES / 4, 256>>>(hs, aggh, aggl);
        k_gemm_mma<<<dim3(2, N_NODES / 128), 256>>>(
            aggh, aggl, whT + l * 65536, wlT + l * 65536, bl[l], tmp, 256);
        k_ln256<<<N_NODES / 8, 256>>>(tmp, hs);
    }
    // layer 4
    k_aggregate<<<N_NODES / 4, 256>>>(hs, aggh, aggl);
    k_gemm_mma<<<dim3(8, N_NODES / 128), 256>>>(
        aggh, aggl, whT + WT_L4_OFF, wlT + WT_L4_OFF, bl[3], hbig, 1024);
    k_ln_big<<<N_NODES / 8, 256>>>(hbig);

    // pool + LN, heads
    k_pool<<<BATCH_B, 256>>>(hbig, pool);
    k_out_init<<<512, 512>>>(bm, bs, out);
    k_head<<<dim3(16, 8, 2), 256>>>(pool, Wm, Ws, out);
}

// round 4
// speedup vs baseline: 1.7375x; 1.1763x over previous
#include <cuda_runtime.h>
#include <cuda_bf16.h>
#include <cuda_fp16.h>
#include <cstdint>

#define N_NODES 32768
#define N_EDGES 524288
#define DIM     256
#define DBIG    1024
#define BATCH_B 128
#define NODES_PER 256

// ---------------- scratch ---------------------------------------------------
__device__ int   g_odeg[N_NODES];
__device__ int   g_ideg[N_NODES];
__device__ int   g_rowptr[N_NODES + 1];
__device__ int   g_cursor[N_NODES];
__device__ int   g_colidx[N_EDGES];
__device__ float g_ns[N_NODES];
__device__ float g_nd[N_NODES];
__device__ __half g_hs[N_NODES * DIM];      // fp16 LN'd + ns-scaled features
__device__ float g_tmp [N_NODES * DIM];     // raw gemm output (bias only)
__device__ float g_hbig[N_NODES * DBIG];    // raw layer-4 gemm output
__device__ float g_pool[BATCH_B * DBIG];
__device__ __nv_bfloat16 g_aggh[N_NODES * DIM];   // aggregated, bf16 hi
__device__ __nv_bfloat16 g_aggl[N_NODES * DIM];   // aggregated, bf16 lo
// transposed + split weights: B[n][k] = W[k][n], bf16 hi/lo, K-major (K=256)
#define WT_L4_OFF 196608
__device__ __nv_bfloat16 g_whT[196608 + 262144];
__device__ __nv_bfloat16 g_wlT[196608 + 262144];

// ---------------- helpers ---------------------------------------------------
__device__ __forceinline__ uint32_t smem_u32(const void* p) {
    uint32_t a;
    asm("{ .reg .u64 t; cvta.to.shared.u64 t, %1; cvt.u32.u64 %0, t; }" : "=r"(a) : "l"(p));
    return a;
}
#define LDSM4(r, addr)                                                          \
    asm volatile("ldmatrix.sync.aligned.m8n8.x4.shared.b16 {%0,%1,%2,%3}, [%4];"\
        : "=r"((r)[0]), "=r"((r)[1]), "=r"((r)[2]), "=r"((r)[3]) : "r"(addr))
#define MMA16816(d, a, b)                                                       \
    asm volatile("mma.sync.aligned.m16n8k16.row.col.f32.bf16.bf16.f32 "         \
        "{%0,%1,%2,%3},{%4,%5,%6,%7},{%8,%9},{%0,%1,%2,%3};"                    \
        : "+f"((d)[0]), "+f"((d)[1]), "+f"((d)[2]), "+f"((d)[3])                \
        : "r"((a)[0]), "r"((a)[1]), "r"((a)[2]), "r"((a)[3]),                   \
          "r"((b)[0]), "r"((b)[1]))

// ---------------- graph setup ------------------------------------------------
__global__ void k_zero() {
    int i = blockIdx.x * blockDim.x + threadIdx.x;
    if (i < N_NODES) { g_odeg[i] = 0; g_ideg[i] = 0; }
}
__global__ void k_count(const int* __restrict__ src, const int* __restrict__ dst) {
    int e = blockIdx.x * blockDim.x + threadIdx.x;
    if (e < N_EDGES) { atomicAdd(&g_odeg[src[e]], 1); atomicAdd(&g_ideg[dst[e]], 1); }
}
__global__ void k_scan() {
    __shared__ int part[1024];
    int tid = threadIdx.x;
    int loc[32];
    int s = 0;
#pragma unroll
    for (int i = 0; i < 32; ++i) { loc[i] = g_ideg[tid * 32 + i]; s += loc[i]; }
    part[tid] = s;
    __syncthreads();
    for (int off = 1; off < 1024; off <<= 1) {
        int v = (tid >= off) ? part[tid - off] : 0;
        __syncthreads();
        part[tid] += v;
        __syncthreads();
    }
    int excl = part[tid] - s;
#pragma unroll
    for (int i = 0; i < 32; ++i) {
        g_rowptr[tid * 32 + i] = excl;
        g_cursor[tid * 32 + i] = excl;
        excl += loc[i];
    }
    if (tid == 1023) g_rowptr[N_NODES] = part[1023];
}
__global__ void k_scatter(const int* __restrict__ src, const int* __restrict__ dst) {
    int e = blockIdx.x * blockDim.x + threadIdx.x;
    if (e < N_EDGES) { int p = atomicAdd(&g_cursor[dst[e]], 1); g_colidx[p] = src[e]; }
}
__global__ void k_norms() {
    int i = blockIdx.x * blockDim.x + threadIdx.x;
    if (i < N_NODES) {
        int od = g_odeg[i], id = g_ideg[i];
        g_ns[i] = (od > 0) ? rsqrtf((float)od) : 1.0f;
        g_nd[i] = (id > 0) ? rsqrtf((float)id) : 1.0f;
    }
}
// hs = half(x * ns)
__global__ void k_scale_x(const float* __restrict__ x, __half* __restrict__ hs) {
    int i = blockIdx.x * blockDim.x + threadIdx.x;   // 4-elem chunk index
    if (i < N_NODES * (DIM / 4)) {
        int row = i >> 6;
        float s = g_ns[row];
        float4 v = *(const float4*)&x[i * 4];
        __half2 h0 = __floats2half2_rn(v.x * s, v.y * s);
        __half2 h1 = __floats2half2_rn(v.z * s, v.w * s);
        uint2 p = make_uint2(*(uint32_t*)&h0, *(uint32_t*)&h1);
        *(uint2*)&hs[i * 4] = p;
    }
}

// ---------------- weight transpose + bf16 split ------------------------------
__global__ void k_prep_w(const float* __restrict__ W, int N,
                         __nv_bfloat16* __restrict__ oh, __nv_bfloat16* __restrict__ ol) {
    __shared__ float t[32][33];
    int n = blockIdx.x * 32 + threadIdx.x;
    int kb = blockIdx.y * 32;
#pragma unroll
    for (int i = 0; i < 4; ++i) {
        int k = kb + threadIdx.y + i * 8;
        t[threadIdx.y + i * 8][threadIdx.x] = W[k * N + n];
    }
    __syncthreads();
    int k2 = kb + threadIdx.x;
#pragma unroll
    for (int i = 0; i < 4; ++i) {
        int n2 = blockIdx.x * 32 + threadIdx.y + i * 8;
        float v = t[threadIdx.x][threadIdx.y + i * 8];
        __nv_bfloat16 h = __float2bfloat16(v);
        oh[n2 * 256 + k2] = h;
        ol[n2 * 256 + k2] = __float2bfloat16(v - __bfloat162float(h));
    }
}

// ---------------- aggregation (fp16 reads, fp32 accum) -> bf16 hi/lo --------
// 8 nodes per 256-thread block; 32 lanes per node, 8 halves per lane.
__device__ __forceinline__ void acc8(float* acc, uint4 v) {
    const __half2* h = (const __half2*)&v;
#pragma unroll
    for (int i = 0; i < 4; ++i) {
        float2 f = __half22float2(h[i]);
        acc[i * 2 + 0] += f.x;
        acc[i * 2 + 1] += f.y;
    }
}
__global__ void __launch_bounds__(256) k_aggregate(const __half* __restrict__ hs,
                                                   __nv_bfloat16* __restrict__ aggh,
                                                   __nv_bfloat16* __restrict__ aggl) {
    int node = blockIdx.x * 8 + (threadIdx.x >> 5);
    int c = (threadIdx.x & 31) * 8;
    int beg = g_rowptr[node], end = g_rowptr[node + 1];
    float acc[8];
#pragma unroll
    for (int i = 0; i < 8; ++i) acc[i] = 0.f;
    int e = beg;
    for (; e + 4 <= end; e += 4) {
        int s0 = g_colidx[e + 0], s1 = g_colidx[e + 1];
        int s2 = g_colidx[e + 2], s3 = g_colidx[e + 3];
        uint4 v0 = *(const uint4*)&hs[s0 * DIM + c];
        uint4 v1 = *(const uint4*)&hs[s1 * DIM + c];
        uint4 v2 = *(const uint4*)&hs[s2 * DIM + c];
        uint4 v3 = *(const uint4*)&hs[s3 * DIM + c];
        acc8(acc, v0); acc8(acc, v1); acc8(acc, v2); acc8(acc, v3);
    }
    for (; e < end; ++e) {
        int s0 = g_colidx[e];
        uint4 v0 = *(const uint4*)&hs[s0 * DIM + c];
        acc8(acc, v0);
    }
    float nd = g_nd[node];
    uint32_t hw[4], lw[4];
#pragma unroll
    for (int i = 0; i < 4; ++i) {
        float a0 = acc[i * 2 + 0] * nd, a1 = acc[i * 2 + 1] * nd;
        __nv_bfloat162 hh = __floats2bfloat162_rn(a0, a1);
        __nv_bfloat162 ll = __floats2bfloat162_rn(a0 - __low2float(hh), a1 - __high2float(hh));
        hw[i] = *(uint32_t*)&hh;
        lw[i] = *(uint32_t*)&ll;
    }
    *(uint4*)&aggh[node * DIM + c] = *(uint4*)hw;
    *(uint4*)&aggl[node * DIM + c] = *(uint4*)lw;
}

// ---------------- bf16 3-term mma.sync GEMM ----------------------------------
#define APAD 40

__global__ void __launch_bounds__(256, 2) k_gemm_mma(
    const __nv_bfloat16* __restrict__ Ah, const __nv_bfloat16* __restrict__ Al,
    const __nv_bfloat16* __restrict__ Bh, const __nv_bfloat16* __restrict__ Bl,
    const float* __restrict__ bias, float* __restrict__ out, int ldout)
{
    __shared__ __align__(16) __nv_bfloat16 sAh[128 * APAD];
    __shared__ __align__(16) __nv_bfloat16 sAl[128 * APAD];
    __shared__ __align__(16) __nv_bfloat16 sBh[128 * APAD];
    __shared__ __align__(16) __nv_bfloat16 sBl[128 * APAD];
    __shared__ float sBias[128];

    int tid = threadIdx.x;
    int wid = tid >> 5, lane = tid & 31;
    int m0 = blockIdx.y * 128, n0 = blockIdx.x * 128;
    int wm = (wid & 1) * 64, wn = (wid >> 1) * 32;

    if (tid < 128) sBias[tid] = bias[n0 + tid];

    float c[4][4][4];
#pragma unroll
    for (int i = 0; i < 4; ++i)
#pragma unroll
        for (int j = 0; j < 4; ++j) {
            c[i][j][0] = 0.f; c[i][j][1] = 0.f; c[i][j][2] = 0.f; c[i][j][3] = 0.f;
        }

    uint32_t uAh = smem_u32(sAh), uAl = smem_u32(sAl);
    uint32_t uBh = smem_u32(sBh), uBl = smem_u32(sBl);
    int aRow = (wm + (lane & 15)) * APAD + (lane >> 4) * 8;
    int bRow = (wn + ((lane >> 4) & 1) * 8 + (lane & 7)) * APAD + ((lane >> 3) & 1) * 8;

    for (int k0 = 0; k0 < 256; k0 += 32) {
#pragma unroll
        for (int it = 0; it < 2; ++it) {
            int s = tid + it * 256;
            int row = s >> 2, seg = s & 3;
            long gA = (long)(m0 + row) * 256 + k0 + seg * 8;
            long gB = (long)(n0 + row) * 256 + k0 + seg * 8;
            int so = row * APAD + seg * 8;
            *(uint4*)&sAh[so] = *(const uint4*)&Ah[gA];
            *(uint4*)&sAl[so] = *(const uint4*)&Al[gA];
            *(uint4*)&sBh[so] = *(const uint4*)&Bh[gB];
            *(uint4*)&sBl[so] = *(const uint4*)&Bl[gB];
        }
        __syncthreads();
#pragma unroll
        for (int kk = 0; kk < 2; ++kk) {
            int kb = kk * 16;
            uint32_t bh[4][2], bl[4][2];
#pragma unroll
            for (int nj2 = 0; nj2 < 2; ++nj2) {
                uint32_t off = (uint32_t)(bRow + nj2 * 16 * APAD + kb) * 2;
                uint32_t r[4];
                LDSM4(r, uBh + off);
                bh[nj2 * 2 + 0][0] = r[0]; bh[nj2 * 2 + 0][1] = r[1];
                bh[nj2 * 2 + 1][0] = r[2]; bh[nj2 * 2 + 1][1] = r[3];
                LDSM4(r, uBl + off);
                bl[nj2 * 2 + 0][0] = r[0]; bl[nj2 * 2 + 0][1] = r[1];
                bl[nj2 * 2 + 1][0] = r[2]; bl[nj2 * 2 + 1][1] = r[3];
            }
#pragma unroll
            for (int mi = 0; mi < 4; ++mi) {
                uint32_t off = (uint32_t)(aRow + mi * 16 * APAD + kb) * 2;
                uint32_t ah[4], al[4];
                LDSM4(ah, uAh + off);
                LDSM4(al, uAl + off);
#pragma unroll
                for (int n8 = 0; n8 < 4; ++n8) {
                    MMA16816(c[mi][n8], ah, bh[n8]);
                    MMA16816(c[mi][n8], ah, bl[n8]);
                    MMA16816(c[mi][n8], al, bh[n8]);
                }
            }
        }
        __syncthreads();
    }

    int lr = lane >> 2, lc = (lane & 3) * 2;
#pragma unroll
    for (int mi = 0; mi < 4; ++mi) {
#pragma unroll
        for (int n8 = 0; n8 < 4; ++n8) {
            int col = wn + n8 * 8 + lc;
            int row = m0 + wm + mi * 16 + lr;
            float b0 = sBias[col], b1 = sBias[col + 1];
            float2 v0 = make_float2(c[mi][n8][0] + b0, c[mi][n8][1] + b1);
            float2 v1 = make_float2(c[mi][n8][2] + b0, c[mi][n8][3] + b1);
            *(float2*)&out[(long)row * ldout + n0 + col] = v0;
            *(float2*)&out[(long)(row + 8) * ldout + n0 + col] = v1;
        }
    }
}

// ---------------- leaky + LN + ns over 256-wide rows -> fp16 hs --------------
__global__ void __launch_bounds__(256) k_ln256(const float* __restrict__ in,
                                               __half* __restrict__ hs) {
    int row = blockIdx.x * 8 + (threadIdx.x >> 5);
    int lane = threadIdx.x & 31;
    const float* r = in + (long)row * DIM;
    float4 v[2];
    float s = 0.f, q = 0.f;
#pragma unroll
    for (int t = 0; t < 2; ++t) {
        float4 x4 = *(const float4*)&r[lane * 4 + t * 128];
        x4.x = (x4.x >= 0.f) ? x4.x : 0.01f * x4.x;
        x4.y = (x4.y >= 0.f) ? x4.y : 0.01f * x4.y;
        x4.z = (x4.z >= 0.f) ? x4.z : 0.01f * x4.z;
        x4.w = (x4.w >= 0.f) ? x4.w : 0.01f * x4.w;
        v[t] = x4;
        s += (x4.x + x4.y) + (x4.z + x4.w);
        q += (x4.x * x4.x + x4.y * x4.y) + (x4.z * x4.z + x4.w * x4.w);
    }
#pragma unroll
    for (int off = 1; off < 32; off <<= 1) {
        s += __shfl_xor_sync(0xffffffffu, s, off);
        q += __shfl_xor_sync(0xffffffffu, q, off);
    }
    float mean = s * (1.0f / 256.0f);
    float var = q * (1.0f / 256.0f) - mean * mean;
    float sc = g_ns[row] * rsqrtf(var + 1e-5f);
    __half* o = hs + (long)row * DIM;
#pragma unroll
    for (int t = 0; t < 2; ++t) {
        __half2 h0 = __floats2half2_rn((v[t].x - mean) * sc, (v[t].y - mean) * sc);
        __half2 h1 = __floats2half2_rn((v[t].z - mean) * sc, (v[t].w - mean) * sc);
        uint2 p = make_uint2(*(uint32_t*)&h0, *(uint32_t*)&h1);
        *(uint2*)&o[lane * 4 + t * 128] = p;
    }
}

// ---------------- fused leaky + LN + mean-pool + pool-LN ---------------------
// One block per batch row (256 nodes x 1024 dims).  8 warps; warp w handles
// node rows w, w+8, ...  Per-node LN entirely in registers; pooled sum in smem.
__global__ void __launch_bounds__(256) k_lnpool(const float* __restrict__ hbig,
                                                float* __restrict__ pool) {
    __shared__ float sp[DBIG];
    __shared__ float ss[8], qq[8];
    __shared__ float s_mean, s_rstd;
    int b = blockIdx.x;
    int tid = threadIdx.x;
    int wid = tid >> 5, lane = tid & 31;

#pragma unroll
    for (int j = 0; j < 4; ++j) sp[tid * 4 + j] = 0.f;
    __syncthreads();

    float acc[32];
#pragma unroll
    for (int i = 0; i < 32; ++i) acc[i] = 0.f;

    for (int r = wid; r < NODES_PER; r += 8) {
        const float* row = hbig + ((long)b * NODES_PER + r) * DBIG;
        float4 v[8];
        float s = 0.f, q = 0.f;
#pragma unroll
        for (int t = 0; t < 8; ++t) {
            float4 x4 = *(const float4*)&row[lane * 4 + t * 128];
            x4.x = (x4.x >= 0.f) ? x4.x : 0.01f * x4.x;
            x4.y = (x4.y >= 0.f) ? x4.y : 0.01f * x4.y;
            x4.z = (x4.z >= 0.f) ? x4.z : 0.01f * x4.z;
            x4.w = (x4.w >= 0.f) ? x4.w : 0.01f * x4.w;
            v[t] = x4;
            s += (x4.x + x4.y) + (x4.z + x4.w);
            q += (x4.x * x4.x + x4.y * x4.y) + (x4.z * x4.z + x4.w * x4.w);
        }
#pragma unroll
        for (int off = 1; off < 32; off <<= 1) {
            s += __shfl_xor_sync(0xffffffffu, s, off);
            q += __shfl_xor_sync(0xffffffffu, q, off);
        }
        float mean = s * (1.0f / 1024.0f);
        float var = q * (1.0f / 1024.0f) - mean * mean;
        float rstd = rsqrtf(var + 1e-5f);
#pragma unroll
        for (int t = 0; t < 8; ++t) {
            acc[t * 4 + 0] += (v[t].x - mean) * rstd;
            acc[t * 4 + 1] += (v[t].y - mean) * rstd;
            acc[t * 4 + 2] += (v[t].z - mean) * rstd;
            acc[t * 4 + 3] += (v[t].w - mean) * rstd;
        }
    }
    // warp partials -> smem pooled sum
#pragma unroll
    for (int t = 0; t < 8; ++t)
#pragma unroll
        for (int j = 0; j < 4; ++j)
            atomicAdd(&sp[lane * 4 + t * 128 + j], acc[t * 4 + j]);
    __syncthreads();

    // LN over pooled mean; thread owns cols tid*4..+3
    const float inv = 1.0f / (float)NODES_PER;
    float v0 = sp[tid * 4 + 0] * inv, v1 = sp[tid * 4 + 1] * inv;
    float v2 = sp[tid * 4 + 2] * inv, v3 = sp[tid * 4 + 3] * inv;
    float s = (v0 + v1) + (v2 + v3);
    float q = (v0 * v0 + v1 * v1) + (v2 * v2 + v3 * v3);
#pragma unroll
    for (int off = 1; off < 32; off <<= 1) {
        s += __shfl_xor_sync(0xffffffffu, s, off);
        q += __shfl_xor_sync(0xffffffffu, q, off);
    }
    if (lane == 0) { ss[wid] = s; qq[wid] = q; }
    __syncthreads();
    if (tid == 0) {
        float S = 0.f, Q = 0.f;
#pragma unroll
        for (int w = 0; w < 8; ++w) { S += ss[w]; Q += qq[w]; }
        float mean = S * (1.0f / 1024.0f);
        float var = Q * (1.0f / 1024.0f) - mean * mean;
        s_mean = mean;
        s_rstd = rsqrtf(var + 1e-5f);
    }
    __syncthreads();
    float mean = s_mean, rstd = s_rstd;
    float4 o;
    o.x = (v0 - mean) * rstd; o.y = (v1 - mean) * rstd;
    o.z = (v2 - mean) * rstd; o.w = (v3 - mean) * rstd;
    *(float4*)&pool[b * DBIG + tid * 4] = o;
}

// ---------------- heads ------------------------------------------------------
__global__ void k_out_init(const float* __restrict__ bm, const float* __restrict__ bs,
                           float* __restrict__ out) {
    int i = blockIdx.x * blockDim.x + threadIdx.x;
    if (i < 2 * BATCH_B * DBIG) {
        int n = i & (DBIG - 1);
        out[i] = (i < BATCH_B * DBIG) ? bm[n] : bs[n];
    }
}
__global__ void __launch_bounds__(256) k_head(const float* __restrict__ pool,
                                              const float* __restrict__ Wm,
                                              const float* __restrict__ Ws,
                                              float* __restrict__ out) {
    const float* W = blockIdx.z ? Ws : Wm;
    float* o = out + blockIdx.z * (BATCH_B * DBIG);
    int n0 = blockIdx.x * 64;
    int kc0 = blockIdx.y * 128;
    int tid = threadIdx.x;
    int col = tid & 63;
    int ty = tid >> 6;
    __shared__ float Ap[32 * 136];
    __shared__ float Wsm[32 * 64];
    float acc[32];
#pragma unroll
    for (int r = 0; r < 32; ++r) acc[r] = 0.f;

    for (int kk = 0; kk < 128; kk += 32) {
#pragma unroll
        for (int t = 0; t < 4; ++t) {
            int s = tid + t * 256;
            int row = s >> 3, kq = s & 7;
            float4 v = *(const float4*)&pool[row * DBIG + kc0 + kk + kq * 4];
            Ap[(kq * 4 + 0) * 136 + row] = v.x;
            Ap[(kq * 4 + 1) * 136 + row] = v.y;
            Ap[(kq * 4 + 2) * 136 + row] = v.z;
            Ap[(kq * 4 + 3) * 136 + row] = v.w;
        }
#pragma unroll
        for (int t = 0; t < 2; ++t) {
            int s = tid + t * 256;
            int kr = s >> 4, c4 = s & 15;
            *(float4*)&Wsm[kr * 64 + c4 * 4] =
                *(const float4*)&W[(kc0 + kk + kr) * DBIG + n0 + c4 * 4];
        }
        __syncthreads();
#pragma unroll
        for (int k = 0; k < 32; ++k) {
            float b = Wsm[k * 64 + col];
#pragma unroll
            for (int r4 = 0; r4 < 8; ++r4) {
                float4 a = *(const float4*)&Ap[k * 136 + ty * 32 + r4 * 4];
                acc[r4 * 4 + 0] += a.x * b;
                acc[r4 * 4 + 1] += a.y * b;
                acc[r4 * 4 + 2] += a.z * b;
                acc[r4 * 4 + 3] += a.w * b;
            }
        }
        __syncthreads();
    }
#pragma unroll
    for (int r = 0; r < 32; ++r)
        atomicAdd(&o[(ty * 32 + r) * DBIG + n0 + col], acc[r]);
}

// ---------------- driver ----------------------------------------------------
extern "C" void kernel_launch(void* const* d_in, const int* in_sizes, int n_in,
                              void* d_out, int out_size) {
    const float* x   = (const float*)d_in[0];
    const int*   src = (const int*)d_in[1];
    const int*   dst = (const int*)d_in[2];
    const float* Wl[4] = { (const float*)d_in[3], (const float*)d_in[5],
                           (const float*)d_in[7], (const float*)d_in[9] };
    const float* bl[4] = { (const float*)d_in[4], (const float*)d_in[6],
                           (const float*)d_in[8], (const float*)d_in[10] };
    const float* Wm = (const float*)d_in[11];
    const float* bm = (const float*)d_in[12];
    const float* Ws = (const float*)d_in[13];
    const float* bs = (const float*)d_in[14];
    float* out = (float*)d_out;

    void *p_hs, *p_tmp, *p_hbig, *p_pool, *p_wh, *p_wl, *p_ah, *p_al;
    cudaGetSymbolAddress(&p_hs,   g_hs);
    cudaGetSymbolAddress(&p_tmp,  g_tmp);
    cudaGetSymbolAddress(&p_hbig, g_hbig);
    cudaGetSymbolAddress(&p_pool, g_pool);
    cudaGetSymbolAddress(&p_wh,   g_whT);
    cudaGetSymbolAddress(&p_wl,   g_wlT);
    cudaGetSymbolAddress(&p_ah,   g_aggh);
    cudaGetSymbolAddress(&p_al,   g_aggl);
    __half* hs  = (__half*)p_hs;
    float* tmp  = (float*)p_tmp;
    float* hbig = (float*)p_hbig;
    float* pool = (float*)p_pool;
    __nv_bfloat16* whT = (__nv_bfloat16*)p_wh;
    __nv_bfloat16* wlT = (__nv_bfloat16*)p_wl;
    __nv_bfloat16* aggh = (__nv_bfloat16*)p_ah;
    __nv_bfloat16* aggl = (__nv_bfloat16*)p_al;

    // graph preprocessing
    k_zero   <<<128, 256>>>();
    k_count  <<<2048, 256>>>(src, dst);
    k_scan   <<<1, 1024>>>();
    k_scatter<<<2048, 256>>>(src, dst);
    k_norms  <<<128, 256>>>();
    k_scale_x<<<8192, 256>>>(x, hs);

    // weight transpose + split (bf16 hi/lo, [n][k])
    dim3 tb(32, 8);
    k_prep_w<<<dim3(8,  8), tb>>>(Wl[0], 256,  whT,            wlT);
    k_prep_w<<<dim3(8,  8), tb>>>(Wl[1], 256,  whT + 65536,    wlT + 65536);
    k_prep_w<<<dim3(8,  8), tb>>>(Wl[2], 256,  whT + 131072,   wlT + 131072);
    k_prep_w<<<dim3(32, 8), tb>>>(Wl[3], 1024, whT + WT_L4_OFF, wlT + WT_L4_OFF);

    // layers 1-3
    for (int l = 0; l < 3; ++l) {
        k_aggregate<<<N_NODES / 8, 256>>>(hs, aggh, aggl);
        k_gemm_mma<<<dim3(2, N_NODES / 128), 256>>>(
            aggh, aggl, whT + l * 65536, wlT + l * 65536, bl[l], tmp, 256);
        k_ln256<<<N_NODES / 8, 256>>>(tmp, hs);
    }
    // layer 4
    k_aggregate<<<N_NODES / 8, 256>>>(hs, aggh, aggl);
    k_gemm_mma<<<dim3(8, N_NODES / 128), 256>>>(
        aggh, aggl, whT + WT_L4_OFF, wlT + WT_L4_OFF, bl[3], hbig, 1024);

    // fused leaky+LN+pool+poolLN, then heads
    k_lnpool<<<BATCH_B, 256>>>(hbig, pool);
    k_out_init<<<512, 512>>>(bm, bs, out);
    k_head<<<dim3(16, 8, 2), 256>>>(pool, Wm, Ws, out);
}